// round 11
// baseline (speedup 1.0000x reference)
#include <cuda_runtime.h>
#include <cuda_fp16.h>

#define N_NODES   100000
#define HIDDEN    48
#define N_TRIPLES 2000000
#define ROW_PAD   64          // u/v rows padded to 64 halves = 128 B

__device__ __align__(16) __half g_u[N_NODES * ROW_PAD];    // fp16 u
__device__ __align__(16) __half g_v[N_NODES * ROW_PAD];    // fp16 v
__device__ __align__(16) float  g_agg[N_NODES * HIDDEN];   // zero-maintained
__device__ __align__(16) float  g_cnt[N_NODES];            // zero-maintained
__device__ __align__(16) float  g_C2[HIDDEN * HIDDEN];
__device__ __align__(16) int4   g_rec[N_TRIPLES];          // {c, n1, n2, w_bits}

// ---------------------------------------------------------------------------
// C2[k][o] = sum_j W3[j][k] * Wu[o][48+j]   (48x48, trivial)
// ---------------------------------------------------------------------------
__global__ void prep_kernel(const float* __restrict__ W3,
                            const float* __restrict__ Wu) {
    int i = blockIdx.x * blockDim.x + threadIdx.x;
    if (i < HIDDEN * HIDDEN) {
        int k = i / HIDDEN, o = i % HIDDEN;
        float s = 0.f;
        #pragma unroll
        for (int j = 0; j < HIDDEN; j++)
            s = fmaf(W3[j * HIDDEN + k], Wu[o * 2 * HIDDEN + HIDDEN + j], s);
        g_C2[i] = s;
    }
}

// ---------------------------------------------------------------------------
// Pack per-triple record {c, n1, n2, w} and accumulate center counts.
// (g_cnt is zero on entry: zero-init at load, re-zeroed by final_kernel.)
// ---------------------------------------------------------------------------
__global__ void pack_kernel(const int* __restrict__ idx,
                            const float* __restrict__ d1a,
                            const float* __restrict__ d2a) {
    int t = blockIdx.x * blockDim.x + threadIdx.x;
    if (t < N_TRIPLES) {
        int c  = idx[3 * t];
        int n1 = idx[3 * t + 1];
        int n2 = idx[3 * t + 2];
        float d1 = __ldg(d1a + t);
        float d2 = __ldg(d2a + t);
        float w = 1.0f + 0.3f * (fabsf(d1 - d2) / (fmaxf(d1, d2) + 1e-8f));
        g_rec[t] = make_int4(c, n1, n2, __float_as_int(w));
        asm volatile("red.global.add.f32 [%0], %1;"
                     :: "l"(g_cnt + c), "f"(1.0f) : "memory");
    }
}

// ---------------------------------------------------------------------------
// u[n][o] = h[n]·Wu1[o];  v[n][o] = h[n]·C2[:,o]  -> both fp16, 128B rows.
// blockDim (12, 32); scalar FFMA inner loop (R4-proven), conflict-free smem.
// ---------------------------------------------------------------------------
__global__ void uv_kernel(const float* __restrict__ h,
                          const float* __restrict__ Wu) {
    __shared__ float4 sA[HIDDEN][12];
    __shared__ float4 sC[HIDDEN][12];
    __shared__ float  sh[64][49];

    int tx = threadIdx.x;                  // 0..11
    int ty = threadIdx.y;                  // 0..31
    int tid = ty * 12 + tx;

    for (int i = tid; i < HIDDEN * 12; i += 384) {
        int k = i / 12, c4 = i % 12;
        sA[k][c4] = make_float4(Wu[(4*c4+0) * 2*HIDDEN + k],
                                Wu[(4*c4+1) * 2*HIDDEN + k],
                                Wu[(4*c4+2) * 2*HIDDEN + k],
                                Wu[(4*c4+3) * 2*HIDDEN + k]);
        sC[k][c4] = ((const float4*)g_C2)[k * 12 + c4];
    }
    int rowBase = blockIdx.x * 64;
    for (int i = tid; i < 64 * 12; i += 384) {
        int r = i / 12, c4 = i % 12;
        int row = rowBase + r;
        float4 v = (row < N_NODES) ? ((const float4*)(h + row * HIDDEN))[c4]
                                   : make_float4(0.f, 0.f, 0.f, 0.f);
        sh[r][4*c4+0] = v.x; sh[r][4*c4+1] = v.y;
        sh[r][4*c4+2] = v.z; sh[r][4*c4+3] = v.w;
    }
    __syncthreads();

    int r0 = ty, r1 = ty + 32;
    float4 u0 = make_float4(0,0,0,0), u1 = u0, v0 = u0, v1 = u0;
    #pragma unroll
    for (int k = 0; k < HIDDEN; k++) {
        float4 wa = sA[k][tx];
        float4 wc = sC[k][tx];
        float h0 = sh[r0][k];
        float h1 = sh[r1][k];
        u0.x = fmaf(h0, wa.x, u0.x); u0.y = fmaf(h0, wa.y, u0.y);
        u0.z = fmaf(h0, wa.z, u0.z); u0.w = fmaf(h0, wa.w, u0.w);
        u1.x = fmaf(h1, wa.x, u1.x); u1.y = fmaf(h1, wa.y, u1.y);
        u1.z = fmaf(h1, wa.z, u1.z); u1.w = fmaf(h1, wa.w, u1.w);
        v0.x = fmaf(h0, wc.x, v0.x); v0.y = fmaf(h0, wc.y, v0.y);
        v0.z = fmaf(h0, wc.z, v0.z); v0.w = fmaf(h0, wc.w, v0.w);
        v1.x = fmaf(h1, wc.x, v1.x); v1.y = fmaf(h1, wc.y, v1.y);
        v1.z = fmaf(h1, wc.z, v1.z); v1.w = fmaf(h1, wc.w, v1.w);
    }

    int row0 = rowBase + r0, row1 = rowBase + r1;
    if (row0 < N_NODES) {
        union { __half2 h2[2]; uint2 u; } cu, cv;
        cu.h2[0] = __floats2half2_rn(u0.x, u0.y); cu.h2[1] = __floats2half2_rn(u0.z, u0.w);
        cv.h2[0] = __floats2half2_rn(v0.x, v0.y); cv.h2[1] = __floats2half2_rn(v0.z, v0.w);
        ((uint2*)(g_u + row0 * ROW_PAD))[tx] = cu.u;
        ((uint2*)(g_v + row0 * ROW_PAD))[tx] = cv.u;
    }
    if (row1 < N_NODES) {
        union { __half2 h2[2]; uint2 u; } cu, cv;
        cu.h2[0] = __floats2half2_rn(u1.x, u1.y); cu.h2[1] = __floats2half2_rn(u1.z, u1.w);
        cv.h2[0] = __floats2half2_rn(v1.x, v1.y); cv.h2[1] = __floats2half2_rn(v1.z, v1.w);
        ((uint2*)(g_u + row1 * ROW_PAD))[tx] = cu.u;
        ((uint2*)(g_v + row1 * ROW_PAD))[tx] = cv.u;
    }
}

// ---------------------------------------------------------------------------
// Per-triple: rec + 3x fp16 one-line gathers + hadd2 + leaky*w + fp32 v4 RED.
// ---------------------------------------------------------------------------
__device__ __forceinline__ void process_triple(int t, int j) {
    int4 r = __ldg(&g_rec[t]);
    float w = __int_as_float(r.w);
    if (j < 12) {
        uint2 au = __ldg((const uint2*)(g_u + r.x * ROW_PAD) + j);
        uint2 a1 = __ldg((const uint2*)(g_v + r.y * ROW_PAD) + j);
        uint2 a2 = __ldg((const uint2*)(g_v + r.z * ROW_PAD) + j);
        __half2 s0 = __hadd2(*(__half2*)&a1.x, *(__half2*)&a2.x);
        __half2 s1 = __hadd2(*(__half2*)&a1.y, *(__half2*)&a2.y);
        s0 = __hadd2(s0, *(__half2*)&au.x);
        s1 = __hadd2(s1, *(__half2*)&au.y);
        float2 f0 = __half22float2(s0);
        float2 f1 = __half22float2(s1);
        float w01 = 0.01f * w;
        float dx = fmaf(fminf(f0.x, 0.f), w01, fmaxf(f0.x, 0.f) * w);
        float dy = fmaf(fminf(f0.y, 0.f), w01, fmaxf(f0.y, 0.f) * w);
        float dz = fmaf(fminf(f1.x, 0.f), w01, fmaxf(f1.x, 0.f) * w);
        float dw = fmaf(fminf(f1.y, 0.f), w01, fmaxf(f1.y, 0.f) * w);
        float* dst = g_agg + r.x * HIDDEN + 4 * j;
        asm volatile("red.global.add.v4.f32 [%0], {%1, %2, %3, %4};"
                     :: "l"(dst), "f"(dx), "f"(dy), "f"(dz), "f"(dw)
                     : "memory");
    }
}

__global__ void __launch_bounds__(256) triple_kernel() {
    int gtid = blockIdx.x * blockDim.x + threadIdx.x;
    int warpId = gtid >> 5;
    int nWarps = (gridDim.x * blockDim.x) >> 5;
    int lane = threadIdx.x & 31;
    int half = lane >> 4;
    int j = lane & 15;

    for (int base = warpId * 4; base < N_TRIPLES; base += nWarps * 4) {
        process_triple(base + half, j);
        process_triple(base + 2 + half, j);
    }
}

// ---------------------------------------------------------------------------
// out = LayerNorm(h + agg / sqrt(max(cnt,1))); re-zeroes agg/cnt for the next
// replay. Variance via E[x^2]-mu^2 so both shuffle trees overlap.
// ---------------------------------------------------------------------------
__global__ void final_kernel(const float* __restrict__ h,
                             const float* __restrict__ gamma,
                             const float* __restrict__ beta,
                             float* __restrict__ out) {
    int tx = threadIdx.x;  // 0..15
    int ty = threadIdx.y;  // 0..15
    int row = blockIdx.x * 16 + ty;
    bool act = tx < 12;

    float rs = rsqrtf(fmaxf(g_cnt[row], 1.0f));
    if (tx == 0) g_cnt[row] = 0.f;

    int b4 = row * 12 + tx;
    float4 x = make_float4(0.f, 0.f, 0.f, 0.f);
    if (act) {
        float4 hv = __ldg((const float4*)h + b4);
        float4 av = ((const float4*)g_agg)[b4];
        x.x = fmaf(av.x, rs, hv.x);
        x.y = fmaf(av.y, rs, hv.y);
        x.z = fmaf(av.z, rs, hv.z);
        x.w = fmaf(av.w, rs, hv.w);
        ((float4*)g_agg)[b4] = make_float4(0.f, 0.f, 0.f, 0.f);
    }

    float s  = x.x + x.y + x.z + x.w;
    float s2 = x.x * x.x + x.y * x.y + x.z * x.z + x.w * x.w;
    #pragma unroll
    for (int m = 8; m; m >>= 1) {
        s  += __shfl_xor_sync(0xffffffffu, s,  m);
        s2 += __shfl_xor_sync(0xffffffffu, s2, m);
    }
    float mu  = s * (1.f / 48.f);
    float var = fmaf(-mu, mu, s2 * (1.f / 48.f));
    float inv = rsqrtf(var + 1e-5f);

    if (act) {
        float4 g = __ldg((const float4*)gamma + tx);
        float4 b = __ldg((const float4*)beta + tx);
        float4 o;
        o.x = fmaf((x.x - mu) * inv, g.x, b.x);
        o.y = fmaf((x.y - mu) * inv, g.y, b.y);
        o.z = fmaf((x.z - mu) * inv, g.z, b.z);
        o.w = fmaf((x.w - mu) * inv, g.w, b.w);
        ((float4*)out)[b4] = o;
    }
}

// ---------------------------------------------------------------------------
extern "C" void kernel_launch(void* const* d_in, const int* in_sizes, int n_in,
                              void* d_out, int out_size) {
    const float* h     = (const float*)d_in[0];
    const int*   idx   = (const int*)d_in[1];
    const float* d1    = (const float*)d_in[2];
    const float* d2    = (const float*)d_in[3];
    const float* W3    = (const float*)d_in[4];
    const float* Wu    = (const float*)d_in[5];
    const float* gamma = (const float*)d_in[6];
    const float* beta  = (const float*)d_in[7];
    float* out = (float*)d_out;

    static cudaStream_t s2 = nullptr;
    static cudaEvent_t evF = nullptr, evJ = nullptr;
    if (!s2) {
        cudaStreamCreateWithFlags(&s2, cudaStreamNonBlocking);
        cudaEventCreateWithFlags(&evF, cudaEventDisableTiming);
        cudaEventCreateWithFlags(&evJ, cudaEventDisableTiming);
    }

    // fork: pack runs concurrently with prep+uv (R6-proven capturable pattern)
    cudaEventRecord(evF, 0);
    cudaStreamWaitEvent(s2, evF, 0);
    pack_kernel<<<(N_TRIPLES + 255) / 256, 256, 0, s2>>>(idx, d1, d2);
    cudaEventRecord(evJ, s2);

    prep_kernel<<<(HIDDEN * HIDDEN + 255) / 256, 256>>>(W3, Wu);
    uv_kernel<<<(N_NODES + 63) / 64, dim3(12, 32)>>>(h, Wu);

    cudaStreamWaitEvent(0, evJ, 0);   // join
    triple_kernel<<<4096, 256>>>();
    final_kernel<<<(N_NODES + 15) / 16, dim3(16, 16)>>>(h, gamma, beta, out);
}

// round 12
// speedup vs baseline: 1.3017x; 1.3017x over previous
#include <cuda_runtime.h>
#include <cuda_fp16.h>

#define N_NODES   100000
#define HIDDEN    48
#define N_TRIPLES 2000000
#define ROW_PAD   64          // u/v rows padded to 64 halves = 128 B

__device__ __align__(16) __half g_u[N_NODES * ROW_PAD];    // fp16 u
__device__ __align__(16) __half g_v[N_NODES * ROW_PAD];    // fp16 v
__device__ __align__(16) float  g_agg[N_NODES * HIDDEN];   // zero-maintained
__device__ __align__(16) float  g_cnt[N_NODES];            // zero-maintained
__device__ __align__(16) float  g_C2[HIDDEN * HIDDEN];

// ---------------------------------------------------------------------------
// C2[k][o] = sum_j W3[j][k] * Wu[o][48+j]   (48x48, trivial)
// ---------------------------------------------------------------------------
__global__ void prep_kernel(const float* __restrict__ W3,
                            const float* __restrict__ Wu) {
    int i = blockIdx.x * blockDim.x + threadIdx.x;
    if (i < HIDDEN * HIDDEN) {
        int k = i / HIDDEN, o = i % HIDDEN;
        float s = 0.f;
        #pragma unroll
        for (int j = 0; j < HIDDEN; j++)
            s = fmaf(W3[j * HIDDEN + k], Wu[o * 2 * HIDDEN + HIDDEN + j], s);
        g_C2[i] = s;
    }
}

// ---------------------------------------------------------------------------
// u[n][o] = h[n]·Wu1[o];  v[n][o] = h[n]·C2[:,o]  -> both fp16, 128B rows.
// R4's exact scalar-FFMA structure; only the u store format is fp16 now.
// blockDim (12, 32).
// ---------------------------------------------------------------------------
__global__ void uv_kernel(const float* __restrict__ h,
                          const float* __restrict__ Wu) {
    __shared__ float4 sA[HIDDEN][12];
    __shared__ float4 sC[HIDDEN][12];
    __shared__ float  sh[64][49];

    int tx = threadIdx.x;                  // 0..11
    int ty = threadIdx.y;                  // 0..31
    int tid = ty * 12 + tx;

    for (int i = tid; i < HIDDEN * 12; i += 384) {
        int k = i / 12, c4 = i % 12;
        sA[k][c4] = make_float4(Wu[(4*c4+0) * 2*HIDDEN + k],
                                Wu[(4*c4+1) * 2*HIDDEN + k],
                                Wu[(4*c4+2) * 2*HIDDEN + k],
                                Wu[(4*c4+3) * 2*HIDDEN + k]);
        sC[k][c4] = ((const float4*)g_C2)[k * 12 + c4];
    }
    int rowBase = blockIdx.x * 64;
    for (int i = tid; i < 64 * 12; i += 384) {
        int r = i / 12, c4 = i % 12;
        int row = rowBase + r;
        float4 v = (row < N_NODES) ? ((const float4*)(h + row * HIDDEN))[c4]
                                   : make_float4(0.f, 0.f, 0.f, 0.f);
        sh[r][4*c4+0] = v.x; sh[r][4*c4+1] = v.y;
        sh[r][4*c4+2] = v.z; sh[r][4*c4+3] = v.w;
    }
    __syncthreads();

    int r0 = ty, r1 = ty + 32;
    float4 u0 = make_float4(0,0,0,0), u1 = u0, v0 = u0, v1 = u0;
    #pragma unroll
    for (int k = 0; k < HIDDEN; k++) {
        float4 wa = sA[k][tx];
        float4 wc = sC[k][tx];
        float h0 = sh[r0][k];
        float h1 = sh[r1][k];
        u0.x = fmaf(h0, wa.x, u0.x); u0.y = fmaf(h0, wa.y, u0.y);
        u0.z = fmaf(h0, wa.z, u0.z); u0.w = fmaf(h0, wa.w, u0.w);
        u1.x = fmaf(h1, wa.x, u1.x); u1.y = fmaf(h1, wa.y, u1.y);
        u1.z = fmaf(h1, wa.z, u1.z); u1.w = fmaf(h1, wa.w, u1.w);
        v0.x = fmaf(h0, wc.x, v0.x); v0.y = fmaf(h0, wc.y, v0.y);
        v0.z = fmaf(h0, wc.z, v0.z); v0.w = fmaf(h0, wc.w, v0.w);
        v1.x = fmaf(h1, wc.x, v1.x); v1.y = fmaf(h1, wc.y, v1.y);
        v1.z = fmaf(h1, wc.z, v1.z); v1.w = fmaf(h1, wc.w, v1.w);
    }

    int row0 = rowBase + r0, row1 = rowBase + r1;
    if (row0 < N_NODES) {
        union { __half2 h2[2]; uint2 u; } cu, cv;
        cu.h2[0] = __floats2half2_rn(u0.x, u0.y); cu.h2[1] = __floats2half2_rn(u0.z, u0.w);
        cv.h2[0] = __floats2half2_rn(v0.x, v0.y); cv.h2[1] = __floats2half2_rn(v0.z, v0.w);
        ((uint2*)(g_u + row0 * ROW_PAD))[tx] = cu.u;
        ((uint2*)(g_v + row0 * ROW_PAD))[tx] = cv.u;
    }
    if (row1 < N_NODES) {
        union { __half2 h2[2]; uint2 u; } cu, cv;
        cu.h2[0] = __floats2half2_rn(u1.x, u1.y); cu.h2[1] = __floats2half2_rn(u1.z, u1.w);
        cv.h2[0] = __floats2half2_rn(v1.x, v1.y); cv.h2[1] = __floats2half2_rn(v1.z, v1.w);
        ((uint2*)(g_u + row1 * ROW_PAD))[tx] = cu.u;
        ((uint2*)(g_v + row1 * ROW_PAD))[tx] = cv.u;
    }
}

// ---------------------------------------------------------------------------
// Per-triple, pack merged in: direct idx/d reads + w compute + fp16 one-line
// gathers + hadd2 + leaky*w + fp32 v4 RED + cnt atomic (lane 12).
// 2 triples per warp per stage, 2 stages unrolled.
// ---------------------------------------------------------------------------
__device__ __forceinline__ void process_triple(const int* __restrict__ idx,
                                               const float* __restrict__ d1a,
                                               const float* __restrict__ d2a,
                                               int t, int j) {
    int b = 3 * t;
    int c  = __ldg(idx + b);
    float d1 = __ldg(d1a + t);
    float d2 = __ldg(d2a + t);
    float w = 1.0f + 0.3f * (fabsf(d1 - d2) / (fmaxf(d1, d2) + 1e-8f));

    if (j < 12) {
        int n1 = __ldg(idx + b + 1);
        int n2 = __ldg(idx + b + 2);
        uint2 au = __ldg((const uint2*)(g_u + c  * ROW_PAD) + j);
        uint2 a1 = __ldg((const uint2*)(g_v + n1 * ROW_PAD) + j);
        uint2 a2 = __ldg((const uint2*)(g_v + n2 * ROW_PAD) + j);
        __half2 s0 = __hadd2(*(__half2*)&a1.x, *(__half2*)&a2.x);
        __half2 s1 = __hadd2(*(__half2*)&a1.y, *(__half2*)&a2.y);
        s0 = __hadd2(s0, *(__half2*)&au.x);
        s1 = __hadd2(s1, *(__half2*)&au.y);
        float2 f0 = __half22float2(s0);
        float2 f1 = __half22float2(s1);
        float w01 = 0.01f * w;
        float dx = fmaf(fminf(f0.x, 0.f), w01, fmaxf(f0.x, 0.f) * w);
        float dy = fmaf(fminf(f0.y, 0.f), w01, fmaxf(f0.y, 0.f) * w);
        float dz = fmaf(fminf(f1.x, 0.f), w01, fmaxf(f1.x, 0.f) * w);
        float dw = fmaf(fminf(f1.y, 0.f), w01, fmaxf(f1.y, 0.f) * w);
        float* dst = g_agg + c * HIDDEN + 4 * j;
        asm volatile("red.global.add.v4.f32 [%0], {%1, %2, %3, %4};"
                     :: "l"(dst), "f"(dx), "f"(dy), "f"(dz), "f"(dw)
                     : "memory");
    } else if (j == 12) {
        asm volatile("red.global.add.f32 [%0], %1;"
                     :: "l"(g_cnt + c), "f"(1.0f) : "memory");
    }
}

__global__ void __launch_bounds__(256) triple_kernel(const int* __restrict__ idx,
                                                     const float* __restrict__ d1a,
                                                     const float* __restrict__ d2a) {
    int gtid = blockIdx.x * blockDim.x + threadIdx.x;
    int warpId = gtid >> 5;
    int nWarps = (gridDim.x * blockDim.x) >> 5;
    int lane = threadIdx.x & 31;
    int half = lane >> 4;
    int j = lane & 15;

    for (int base = warpId * 4; base < N_TRIPLES; base += nWarps * 4) {
        process_triple(idx, d1a, d2a, base + half, j);
        process_triple(idx, d1a, d2a, base + 2 + half, j);
    }
}

// ---------------------------------------------------------------------------
// out = LayerNorm(h + agg / sqrt(max(cnt,1))); re-zeroes agg/cnt (R4-exact).
// blockDim (16,16): thread handles 3 consecutive cols; 16-lane shuffles.
// ---------------------------------------------------------------------------
__global__ void final_kernel(const float* __restrict__ h,
                             const float* __restrict__ gamma,
                             const float* __restrict__ beta,
                             float* __restrict__ out) {
    int tx = threadIdx.x;  // 0..15
    int ty = threadIdx.y;  // 0..15
    int row = blockIdx.x * 16 + ty;
    if (row >= N_NODES) return;

    float rs = rsqrtf(fmaxf(g_cnt[row], 1.0f));
    int base = row * HIDDEN + tx * 3;
    float x0 = h[base]     + g_agg[base]     * rs;
    float x1 = h[base + 1] + g_agg[base + 1] * rs;
    float x2 = h[base + 2] + g_agg[base + 2] * rs;

    // re-zero for next replay (each thread zeroes exactly what it read)
    g_agg[base] = 0.f; g_agg[base + 1] = 0.f; g_agg[base + 2] = 0.f;
    if (tx == 0) g_cnt[row] = 0.f;

    float s = x0 + x1 + x2;
    #pragma unroll
    for (int m = 8; m; m >>= 1) s += __shfl_xor_sync(0xffffffffu, s, m);
    float mu = s * (1.f / 48.f);

    float e0 = x0 - mu, e1 = x1 - mu, e2 = x2 - mu;
    float q = e0 * e0 + e1 * e1 + e2 * e2;
    #pragma unroll
    for (int m = 8; m; m >>= 1) q += __shfl_xor_sync(0xffffffffu, q, m);
    float inv = rsqrtf(q * (1.f / 48.f) + 1e-5f);

    int o = tx * 3;
    out[base]     = e0 * inv * gamma[o]     + beta[o];
    out[base + 1] = e1 * inv * gamma[o + 1] + beta[o + 1];
    out[base + 2] = e2 * inv * gamma[o + 2] + beta[o + 2];
}

// ---------------------------------------------------------------------------
extern "C" void kernel_launch(void* const* d_in, const int* in_sizes, int n_in,
                              void* d_out, int out_size) {
    const float* h     = (const float*)d_in[0];
    const int*   idx   = (const int*)d_in[1];
    const float* d1    = (const float*)d_in[2];
    const float* d2    = (const float*)d_in[3];
    const float* W3    = (const float*)d_in[4];
    const float* Wu    = (const float*)d_in[5];
    const float* gamma = (const float*)d_in[6];
    const float* beta  = (const float*)d_in[7];
    float* out = (float*)d_out;

    prep_kernel<<<(HIDDEN * HIDDEN + 255) / 256, 256>>>(W3, Wu);
    uv_kernel<<<(N_NODES + 63) / 64, dim3(12, 32)>>>(h, Wu);
    triple_kernel<<<4096, 256>>>(idx, d1, d2);
    final_kernel<<<(N_NODES + 15) / 16, dim3(16, 16)>>>(h, gamma, beta, out);
}

// round 14
// speedup vs baseline: 1.4328x; 1.1008x over previous
#include <cuda_runtime.h>
#include <cuda_fp16.h>

#define N_NODES   100000
#define HIDDEN    48
#define N_TRIPLES 2000000
#define ROW_PAD   64          // u/v rows padded to 64 halves = 128 B

__device__ __align__(16) __half g_u[N_NODES * ROW_PAD];    // fp16 u
__device__ __align__(16) __half g_v[N_NODES * ROW_PAD];    // fp16 v
__device__ __align__(16) float  g_agg[N_NODES * HIDDEN];   // zero-maintained
__device__ __align__(16) float  g_cnt[N_NODES];            // zero-maintained
__device__ __align__(16) float  g_C2[HIDDEN * HIDDEN];

// ---------------------------------------------------------------------------
// C2[k][o] = sum_j W3[j][k] * Wu[o][48+j]   (48x48, trivial)
// ---------------------------------------------------------------------------
__global__ void prep_kernel(const float* __restrict__ W3,
                            const float* __restrict__ Wu) {
    int i = blockIdx.x * blockDim.x + threadIdx.x;
    if (i < HIDDEN * HIDDEN) {
        int k = i / HIDDEN, o = i % HIDDEN;
        float s = 0.f;
        #pragma unroll
        for (int j = 0; j < HIDDEN; j++)
            s = fmaf(W3[j * HIDDEN + k], Wu[o * 2 * HIDDEN + HIDDEN + j], s);
        g_C2[i] = s;
    }
}

// ---------------------------------------------------------------------------
// u[n][o] = h[n]·Wu1[o];  v[n][o] = h[n]·C2[:,o]  -> both fp16, 128B rows.
// 4-row register tiling: blockDim (12, 32), 128-row tiles, 32 accumulators.
// ---------------------------------------------------------------------------
__global__ void uv_kernel(const float* __restrict__ h,
                          const float* __restrict__ Wu) {
    __shared__ float4 sA[HIDDEN][12];
    __shared__ float4 sC[HIDDEN][12];
    __shared__ float  sh[128][49];

    int tx = threadIdx.x;                  // 0..11
    int ty = threadIdx.y;                  // 0..31
    int tid = ty * 12 + tx;

    for (int i = tid; i < HIDDEN * 12; i += 384) {
        int k = i / 12, c4 = i % 12;
        sA[k][c4] = make_float4(Wu[(4*c4+0) * 2*HIDDEN + k],
                                Wu[(4*c4+1) * 2*HIDDEN + k],
                                Wu[(4*c4+2) * 2*HIDDEN + k],
                                Wu[(4*c4+3) * 2*HIDDEN + k]);
        sC[k][c4] = ((const float4*)g_C2)[k * 12 + c4];
    }
    int rowBase = blockIdx.x * 128;
    for (int i = tid; i < 128 * 12; i += 384) {
        int r = i / 12, c4 = i % 12;
        int row = rowBase + r;
        float4 v = (row < N_NODES) ? ((const float4*)(h + row * HIDDEN))[c4]
                                   : make_float4(0.f, 0.f, 0.f, 0.f);
        sh[r][4*c4+0] = v.x; sh[r][4*c4+1] = v.y;
        sh[r][4*c4+2] = v.z; sh[r][4*c4+3] = v.w;
    }
    __syncthreads();

    int r0 = ty, r1 = ty + 32, r2 = ty + 64, r3 = ty + 96;
    float4 u0 = make_float4(0,0,0,0), u1 = u0, u2 = u0, u3 = u0;
    float4 v0 = u0, v1 = u0, v2 = u0, v3 = u0;
    #pragma unroll
    for (int k = 0; k < HIDDEN; k++) {
        float4 wa = sA[k][tx];
        float4 wc = sC[k][tx];
        float h0 = sh[r0][k];
        float h1 = sh[r1][k];
        float h2 = sh[r2][k];
        float h3 = sh[r3][k];
        u0.x = fmaf(h0, wa.x, u0.x); u0.y = fmaf(h0, wa.y, u0.y);
        u0.z = fmaf(h0, wa.z, u0.z); u0.w = fmaf(h0, wa.w, u0.w);
        u1.x = fmaf(h1, wa.x, u1.x); u1.y = fmaf(h1, wa.y, u1.y);
        u1.z = fmaf(h1, wa.z, u1.z); u1.w = fmaf(h1, wa.w, u1.w);
        u2.x = fmaf(h2, wa.x, u2.x); u2.y = fmaf(h2, wa.y, u2.y);
        u2.z = fmaf(h2, wa.z, u2.z); u2.w = fmaf(h2, wa.w, u2.w);
        u3.x = fmaf(h3, wa.x, u3.x); u3.y = fmaf(h3, wa.y, u3.y);
        u3.z = fmaf(h3, wa.z, u3.z); u3.w = fmaf(h3, wa.w, u3.w);
        v0.x = fmaf(h0, wc.x, v0.x); v0.y = fmaf(h0, wc.y, v0.y);
        v0.z = fmaf(h0, wc.z, v0.z); v0.w = fmaf(h0, wc.w, v0.w);
        v1.x = fmaf(h1, wc.x, v1.x); v1.y = fmaf(h1, wc.y, v1.y);
        v1.z = fmaf(h1, wc.z, v1.z); v1.w = fmaf(h1, wc.w, v1.w);
        v2.x = fmaf(h2, wc.x, v2.x); v2.y = fmaf(h2, wc.y, v2.y);
        v2.z = fmaf(h2, wc.z, v2.z); v2.w = fmaf(h2, wc.w, v2.w);
        v3.x = fmaf(h3, wc.x, v3.x); v3.y = fmaf(h3, wc.y, v3.y);
        v3.z = fmaf(h3, wc.z, v3.z); v3.w = fmaf(h3, wc.w, v3.w);
    }

    #pragma unroll
    for (int q = 0; q < 4; q++) {
        int row = rowBase + ty + 32 * q;
        if (row < N_NODES) {
            float4 uu = (q == 0) ? u0 : (q == 1) ? u1 : (q == 2) ? u2 : u3;
            float4 vv = (q == 0) ? v0 : (q == 1) ? v1 : (q == 2) ? v2 : v3;
            union { __half2 h2[2]; uint2 u; } cu, cv;
            cu.h2[0] = __floats2half2_rn(uu.x, uu.y);
            cu.h2[1] = __floats2half2_rn(uu.z, uu.w);
            cv.h2[0] = __floats2half2_rn(vv.x, vv.y);
            cv.h2[1] = __floats2half2_rn(vv.z, vv.w);
            ((uint2*)(g_u + row * ROW_PAD))[tx] = cu.u;
            ((uint2*)(g_v + row * ROW_PAD))[tx] = cv.u;
        }
    }
}

// ---------------------------------------------------------------------------
// Per-triple, pack merged in: direct idx/d reads + w compute + fp16 one-line
// gathers + hadd2 + leaky*w + fp32 v4 RED + cnt atomic (lane 12).
// ---------------------------------------------------------------------------
__device__ __forceinline__ void process_triple(const int* __restrict__ idx,
                                               const float* __restrict__ d1a,
                                               const float* __restrict__ d2a,
                                               int t, int j) {
    int b = 3 * t;
    int c  = __ldg(idx + b);
    float d1 = __ldg(d1a + t);
    float d2 = __ldg(d2a + t);
    float w = 1.0f + 0.3f * (fabsf(d1 - d2) / (fmaxf(d1, d2) + 1e-8f));

    if (j < 12) {
        int n1 = __ldg(idx + b + 1);
        int n2 = __ldg(idx + b + 2);
        uint2 au = __ldg((const uint2*)(g_u + c  * ROW_PAD) + j);
        uint2 a1 = __ldg((const uint2*)(g_v + n1 * ROW_PAD) + j);
        uint2 a2 = __ldg((const uint2*)(g_v + n2 * ROW_PAD) + j);
        __half2 s0 = __hadd2(*(__half2*)&a1.x, *(__half2*)&a2.x);
        __half2 s1 = __hadd2(*(__half2*)&a1.y, *(__half2*)&a2.y);
        s0 = __hadd2(s0, *(__half2*)&au.x);
        s1 = __hadd2(s1, *(__half2*)&au.y);
        float2 f0 = __half22float2(s0);
        float2 f1 = __half22float2(s1);
        float w01 = 0.01f * w;
        float dx = fmaf(fminf(f0.x, 0.f), w01, fmaxf(f0.x, 0.f) * w);
        float dy = fmaf(fminf(f0.y, 0.f), w01, fmaxf(f0.y, 0.f) * w);
        float dz = fmaf(fminf(f1.x, 0.f), w01, fmaxf(f1.x, 0.f) * w);
        float dw = fmaf(fminf(f1.y, 0.f), w01, fmaxf(f1.y, 0.f) * w);
        float* dst = g_agg + c * HIDDEN + 4 * j;
        asm volatile("red.global.add.v4.f32 [%0], {%1, %2, %3, %4};"
                     :: "l"(dst), "f"(dx), "f"(dy), "f"(dz), "f"(dw)
                     : "memory");
    } else if (j == 12) {
        asm volatile("red.global.add.f32 [%0], %1;"
                     :: "l"(g_cnt + c), "f"(1.0f) : "memory");
    }
}

__global__ void __launch_bounds__(256) triple_kernel(const int* __restrict__ idx,
                                                     const float* __restrict__ d1a,
                                                     const float* __restrict__ d2a) {
    int gtid = blockIdx.x * blockDim.x + threadIdx.x;
    int warpId = gtid >> 5;
    int nWarps = (gridDim.x * blockDim.x) >> 5;
    int lane = threadIdx.x & 31;
    int half = lane >> 4;
    int j = lane & 15;

    for (int base = warpId * 4; base < N_TRIPLES; base += nWarps * 4) {
        process_triple(idx, d1a, d2a, base + half, j);
        process_triple(idx, d1a, d2a, base + 2 + half, j);
    }
}

// ---------------------------------------------------------------------------
// out = LayerNorm(h + agg / sqrt(max(cnt,1))); re-zeroes agg/cnt (R12-exact).
// ---------------------------------------------------------------------------
__global__ void final_kernel(const float* __restrict__ h,
                             const float* __restrict__ gamma,
                             const float* __restrict__ beta,
                             float* __restrict__ out) {
    int tx = threadIdx.x;  // 0..15
    int ty = threadIdx.y;  // 0..15
    int row = blockIdx.x * 16 + ty;
    if (row >= N_NODES) return;

    float rs = rsqrtf(fmaxf(g_cnt[row], 1.0f));
    int base = row * HIDDEN + tx * 3;
    float x0 = h[base]     + g_agg[base]     * rs;
    float x1 = h[base + 1] + g_agg[base + 1] * rs;
    float x2 = h[base + 2] + g_agg[base + 2] * rs;

    g_agg[base] = 0.f; g_agg[base + 1] = 0.f; g_agg[base + 2] = 0.f;
    if (tx == 0) g_cnt[row] = 0.f;

    float s = x0 + x1 + x2;
    #pragma unroll
    for (int m = 8; m; m >>= 1) s += __shfl_xor_sync(0xffffffffu, s, m);
    float mu = s * (1.f / 48.f);

    float e0 = x0 - mu, e1 = x1 - mu, e2 = x2 - mu;
    float q = e0 * e0 + e1 * e1 + e2 * e2;
    #pragma unroll
    for (int m = 8; m; m >>= 1) q += __shfl_xor_sync(0xffffffffu, q, m);
    float inv = rsqrtf(q * (1.f / 48.f) + 1e-5f);

    int o = tx * 3;
    out[base]     = e0 * inv * gamma[o]     + beta[o];
    out[base + 1] = e1 * inv * gamma[o + 1] + beta[o + 1];
    out[base + 2] = e2 * inv * gamma[o + 2] + beta[o + 2];
}

// ---------------------------------------------------------------------------
extern "C" void kernel_launch(void* const* d_in, const int* in_sizes, int n_in,
                              void* d_out, int out_size) {
    const float* h     = (const float*)d_in[0];
    const int*   idx   = (const int*)d_in[1];
    const float* d1    = (const float*)d_in[2];
    const float* d2    = (const float*)d_in[3];
    const float* W3    = (const float*)d_in[4];
    const float* Wu    = (const float*)d_in[5];
    const float* gamma = (const float*)d_in[6];
    const float* beta  = (const float*)d_in[7];
    float* out = (float*)d_out;

    prep_kernel<<<(HIDDEN * HIDDEN + 255) / 256, 256>>>(W3, Wu);
    uv_kernel<<<(N_NODES + 127) / 128, dim3(12, 32)>>>(h, Wu);
    triple_kernel<<<4096, 256>>>(idx, d1, d2);
    final_kernel<<<(N_NODES + 15) / 16, dim3(16, 16)>>>(h, gamma, beta, out);
}